// round 15
// baseline (speedup 1.0000x reference)
#include <cuda_runtime.h>
#include <cuda_bf16.h>
#include <cuda_fp16.h>
#include <math.h>

#define NN 50000
#define EE 800000
#define F 128
#define BN_EPS 1e-5f
#define SCAN_B 1024

// ---------------- scratch (16B-aligned where vector-accessed) ----------------
__device__ __align__(16) unsigned g_feath[NN * 64];   // feature as half2 [n][64]
__device__ __align__(16) unsigned g_aggh[NN * 192];   // agg features half2 [n][192]
__device__ __align__(16) unsigned g_Mt[128 * 192];    // M^T half2: [o][k/2]
__device__ __align__(16) float4 g_cp[NN * 2];         // {cx,cy,cz,p0},{p1,p2,-,-}
__device__ float g_sum[F];
__device__ float g_sum2[F];
__device__ float g_den[NN];
__device__ int   g_cnt[NN];
__device__ int   g_off[NN + 1];
__device__ int   g_cur[NN];
__device__ __align__(16) long long g_pack[EE];        // {w (hi), src*4+order (lo)} CSR

__device__ __forceinline__ unsigned h2u(float a, float b) {
    __half2 h = __floats2half2_rn(a, b);
    return *reinterpret_cast<unsigned*>(&h);
}

// ---------------- kernels ----------------
// per-node: proj = attW^T f; pack coords+proj; convert feature to half; zero cnt/den
__global__ void k_proj(const float* __restrict__ feat,
                       const float* __restrict__ coords,
                       const float* __restrict__ attW, int n) {
    int w = (blockIdx.x * blockDim.x + threadIdx.x) >> 5;
    int lane = threadIdx.x & 31;
    if (w >= n) return;
    float4 f = reinterpret_cast<const float4*>(feat + (size_t)w * F)[lane];
    reinterpret_cast<uint2*>(g_feath)[w * 32 + lane] =
        make_uint2(h2u(f.x, f.y), h2u(f.z, f.w));
    const float4* aw = reinterpret_cast<const float4*>(attW);
    float4 w0 = aw[lane], w1 = aw[32 + lane], w2 = aw[64 + lane];
    float a0 = f.x * w0.x + f.y * w0.y + f.z * w0.z + f.w * w0.w;
    float a1 = f.x * w1.x + f.y * w1.y + f.z * w1.z + f.w * w1.w;
    float a2 = f.x * w2.x + f.y * w2.y + f.z * w2.z + f.w * w2.w;
#pragma unroll
    for (int off = 16; off; off >>= 1) {
        a0 += __shfl_down_sync(0xffffffffu, a0, off);
        a1 += __shfl_down_sync(0xffffffffu, a1, off);
        a2 += __shfl_down_sync(0xffffffffu, a2, off);
    }
    if (lane == 0) {
        float cx = coords[w * 3 + 0], cy = coords[w * 3 + 1], cz = coords[w * 3 + 2];
        g_cp[w * 2 + 0] = make_float4(cx, cy, cz, a0);
        g_cp[w * 2 + 1] = make_float4(a1, a2, 0.f, 0.f);
        g_cnt[w] = 0;
        g_den[w] = 0.f;
    }
}

// count pass: histogram of dst
__global__ void k_count(const int* __restrict__ dst, int e) {
    int i = blockIdx.x * blockDim.x + threadIdx.x;
    if (i < e) atomicAdd(&g_cnt[dst[i]], 1);
}

// single-kernel exclusive scan: one block of 1024 threads loops with carry
__global__ void k_scan(int n, int e) {
    __shared__ int swarp[32];
    __shared__ int scarry;
    int tid = threadIdx.x;
    int lane = tid & 31;
    int wid = tid >> 5;
    if (tid == 0) scarry = 0;
    __syncthreads();
    for (int chunk = 0; chunk < n; chunk += SCAN_B) {
        int g = chunk + tid;
        int v = (g < n) ? g_cnt[g] : 0;
        int x = v;
#pragma unroll
        for (int off = 1; off < 32; off <<= 1) {
            int t = __shfl_up_sync(0xffffffffu, x, off);
            if (lane >= off) x += t;
        }
        if (lane == 31) swarp[wid] = x;
        __syncthreads();
        if (wid == 0) {
            int y = swarp[lane];
#pragma unroll
            for (int off = 1; off < 32; off <<= 1) {
                int t = __shfl_up_sync(0xffffffffu, y, off);
                if (lane >= off) y += t;
            }
            swarp[lane] = y;
        }
        __syncthreads();
        int prefix = (wid > 0) ? swarp[wid - 1] : 0;
        int excl = x - v + prefix + scarry;
        if (g < n) {
            g_off[g] = excl;
            g_cur[g] = excl;
        }
        __syncthreads();
        if (tid == 0) scarry += swarp[31];
        __syncthreads();
    }
    if (tid == 0) g_off[n] = e;
}

// edge pass: att/exp/w; den += ex (no-return REDG); CSR scatter of {w,id}
__global__ void k_edge(const int* __restrict__ src, const int* __restrict__ dst,
                       const int* __restrict__ order, int e) {
    int i = blockIdx.x * blockDim.x + threadIdx.x;
    if (i >= e) return;
    int s = src[i], d = dst[i];
    float4 cs0 = g_cp[s * 2 + 0];
    float4 cs1 = g_cp[s * 2 + 1];
    float4 cd0 = g_cp[d * 2 + 0];
    float dx = cs0.x - cd0.x, dy = cs0.y - cd0.y, dz = cs0.z - cd0.z;
    float a = dx * cs0.w + dy * cs1.x + dz * cs1.y;
    float inv = 1.f / (dx * dx + dy * dy + dz * dz + 1.f);
    float ex = __expf(a);
    float w = ex * inv;
    atomicAdd(&g_den[d], ex);
    int pos = atomicAdd(&g_cur[d], 1);
    g_pack[pos] = ((long long)__float_as_int(w) << 32) | (unsigned int)(s * 4 + order[i]);
}

// aggregation: warp per dst; smem-staged records; fp16 feature gathers;
// den read once; no atomics.
__global__ void k_agg(int n) {
    __shared__ long long srec[8][33];
    int wwid = threadIdx.x >> 5;
    int node = (blockIdx.x * blockDim.x + threadIdx.x) >> 5;
    int lane = threadIdx.x & 31;
    if (node >= n) return;
    int beg = g_off[node], end = g_off[node + 1];
    float den = g_den[node];
    float invden = 1.f / (den > 0.f ? den : 1.f);
    float4 a0 = make_float4(0.f, 0.f, 0.f, 0.f);
    float4 a1 = a0, a2 = a0;
    const uint2* f2 = reinterpret_cast<const uint2*>(g_feath);
    for (int base = beg; base < end; base += 32) {
        int idx = base + lane;
        if (idx < end) srec[wwid][lane] = g_pack[idx];
        __syncwarp();
        int cnt = min(32, end - base);
#pragma unroll 4
        for (int j = 0; j < cnt; j++) {
            long long p = srec[wwid][j];
            int id = (int)(unsigned int)p;
            int s = id >> 2, k = id & 3;
            float w = __int_as_float((int)(p >> 32));
            uint2 hv = f2[(size_t)s * 32 + lane];
            __half2 h0 = *reinterpret_cast<__half2*>(&hv.x);
            __half2 h1 = *reinterpret_cast<__half2*>(&hv.y);
            float2 v01 = __half22float2(h0);
            float2 v23 = __half22float2(h1);
            if (k == 0) {
                a0.x += w * v01.x; a0.y += w * v01.y; a0.z += w * v23.x; a0.w += w * v23.y;
            } else if (k == 1) {
                a1.x += w * v01.x; a1.y += w * v01.y; a1.z += w * v23.x; a1.w += w * v23.y;
            } else {
                a2.x += w * v01.x; a2.y += w * v01.y; a2.z += w * v23.x; a2.w += w * v23.y;
            }
        }
        __syncwarp();
    }
    uint2* gp = reinterpret_cast<uint2*>(g_aggh);
    gp[node * 96 +  0 + lane] = make_uint2(h2u(a0.x * invden, a0.y * invden),
                                           h2u(a0.z * invden, a0.w * invden));
    gp[node * 96 + 32 + lane] = make_uint2(h2u(a1.x * invden, a1.y * invden),
                                           h2u(a1.z * invden, a1.w * invden));
    gp[node * 96 + 64 + lane] = make_uint2(h2u(a2.x * invden, a2.y * invden),
                                           h2u(a2.z * invden, a2.w * invden));
}

// fold: M[r][o] = sum_j linear[r][j]*mlp_w[o][j]; store half TRANSPOSED [o][k/2]
__global__ void k_prep(const float* __restrict__ lin, const float* __restrict__ W) {
    extern __shared__ float smem[];
    float* swT = smem;              // [128][129]
    float* sL = smem + 128 * 129;   // [16][128]
    int t = threadIdx.x;
    int r0 = blockIdx.x * 16;
    if (blockIdx.x == 0) { g_sum[t] = 0.f; g_sum2[t] = 0.f; }
#pragma unroll 4
    for (int j = 0; j < F; j++)
        swT[t * 129 + j] = W[j * F + t];
    for (int idx = t; idx < 16 * F; idx += F)
        sL[idx] = lin[(size_t)r0 * F + idx];
    __syncthreads();
    float acc[16];
#pragma unroll
    for (int r = 0; r < 16; r++) acc[r] = 0.f;
#pragma unroll 4
    for (int j = 0; j < F; j++) {
        float wv = swT[j * 129 + t];
#pragma unroll
        for (int r = 0; r < 16; r++) acc[r] += sL[r * F + j] * wv;
    }
#pragma unroll
    for (int j = 0; j < 8; j++)
        g_Mt[t * 192 + r0 / 2 + j] = h2u(acc[2 * j], acc[2 * j + 1]);
}

// fused output GEMM (fp16 tensor cores m16n8k16, fp32 accum)
__global__ void __launch_bounds__(256, 2)
k_out_t(const float* __restrict__ mlp_b, float* __restrict__ out, int n) {
    __shared__ unsigned As2[128 * 20];
    __shared__ unsigned Bs2[128 * 20];
    __shared__ float ssum[128], ssum2[128];
    int tid = threadIdx.x;
    int lane = tid & 31;
    int wid = tid >> 5;
    int wm = wid >> 1;
    int wn = wid & 1;
    int row0 = blockIdx.x * 128;

    if (tid < 128) { ssum[tid] = 0.f; ssum2[tid] = 0.f; }

    float c[2][8][4];
#pragma unroll
    for (int i = 0; i < 2; i++)
#pragma unroll
        for (int j = 0; j < 8; j++)
#pragma unroll
            for (int q = 0; q < 4; q++) c[i][j][q] = 0.f;

    int arow[2], aq[2];
#pragma unroll
    for (int i = 0; i < 2; i++) {
        int lidx = i * 256 + tid;
        arow[i] = lidx >> 2;
        aq[i] = (lidx & 3) * 4;
    }

    uint4 pa[2], pb[2];
#pragma unroll
    for (int i = 0; i < 2; i++) {
        pa[i] = make_uint4(0, 0, 0, 0);
        if (row0 + arow[i] < n)
            pa[i] = *reinterpret_cast<const uint4*>(g_aggh + (size_t)(row0 + arow[i]) * 192 + aq[i]);
        pb[i] = *reinterpret_cast<const uint4*>(g_Mt + (size_t)arow[i] * 192 + aq[i]);
    }

    for (int k0 = 0; k0 < 384; k0 += 32) {
        __syncthreads();
#pragma unroll
        for (int i = 0; i < 2; i++) {
            unsigned* ap = &As2[arow[i] * 20 + aq[i]];
            ap[0] = pa[i].x; ap[1] = pa[i].y; ap[2] = pa[i].z; ap[3] = pa[i].w;
            unsigned* bp = &Bs2[arow[i] * 20 + aq[i]];
            bp[0] = pb[i].x; bp[1] = pb[i].y; bp[2] = pb[i].z; bp[3] = pb[i].w;
        }
        __syncthreads();

        int kn = k0 + 32;
        if (kn < 384) {
            int kb = kn >> 1;
#pragma unroll
            for (int i = 0; i < 2; i++) {
                pa[i] = make_uint4(0, 0, 0, 0);
                if (row0 + arow[i] < n)
                    pa[i] = *reinterpret_cast<const uint4*>(g_aggh + (size_t)(row0 + arow[i]) * 192 + kb + aq[i]);
                pb[i] = *reinterpret_cast<const uint4*>(g_Mt + (size_t)arow[i] * 192 + kb + aq[i]);
            }
        }

#pragma unroll
        for (int kofs = 0; kofs < 16; kofs += 8) {
            unsigned a[2][4];
#pragma unroll
            for (int mt = 0; mt < 2; mt++) {
                int r = wm * 32 + mt * 16 + (lane >> 2);
                int kp = kofs + (lane & 3);
                a[mt][0] = As2[r * 20 + kp];
                a[mt][1] = As2[(r + 8) * 20 + kp];
                a[mt][2] = As2[r * 20 + kp + 4];
                a[mt][3] = As2[(r + 8) * 20 + kp + 4];
            }
#pragma unroll
            for (int nt = 0; nt < 8; nt++) {
                int col = wn * 64 + nt * 8 + (lane >> 2);
                int kp = kofs + (lane & 3);
                unsigned b0 = Bs2[col * 20 + kp];
                unsigned b1 = Bs2[col * 20 + kp + 4];
#pragma unroll
                for (int mt = 0; mt < 2; mt++) {
                    asm volatile(
                        "mma.sync.aligned.m16n8k16.row.col.f32.f16.f16.f32 "
                        "{%0,%1,%2,%3}, {%4,%5,%6,%7}, {%8,%9}, {%0,%1,%2,%3};"
                        : "+f"(c[mt][nt][0]), "+f"(c[mt][nt][1]),
                          "+f"(c[mt][nt][2]), "+f"(c[mt][nt][3])
                        : "r"(a[mt][0]), "r"(a[mt][1]), "r"(a[mt][2]), "r"(a[mt][3]),
                          "r"(b0), "r"(b1));
                }
            }
        }
    }
    __syncthreads();

    float s0[8][2], s2r[8][2];
#pragma unroll
    for (int nt = 0; nt < 8; nt++) {
        s0[nt][0] = 0.f; s0[nt][1] = 0.f;
        s2r[nt][0] = 0.f; s2r[nt][1] = 0.f;
    }
#pragma unroll
    for (int nt = 0; nt < 8; nt++) {
        int colb = wn * 64 + nt * 8 + (lane & 3) * 2;
        float b0 = mlp_b[colb], b1 = mlp_b[colb + 1];
#pragma unroll
        for (int mt = 0; mt < 2; mt++) {
            int rowa = row0 + wm * 32 + mt * 16 + (lane >> 2);
#pragma unroll
            for (int h = 0; h < 2; h++) {
                int row = rowa + h * 8;
                if (row >= n) continue;
                float y0 = c[mt][nt][h * 2 + 0] + b0;
                float y1 = c[mt][nt][h * 2 + 1] + b1;
                y0 = y0 > 0.f ? y0 : 0.f;
                y1 = y1 > 0.f ? y1 : 0.f;
                out[(size_t)row * F + colb] = y0;
                out[(size_t)row * F + colb + 1] = y1;
                s0[nt][0] += y0; s0[nt][1] += y1;
                s2r[nt][0] += y0 * y0; s2r[nt][1] += y1 * y1;
            }
        }
    }
#pragma unroll
    for (int nt = 0; nt < 8; nt++) {
        int colb = wn * 64 + nt * 8 + (lane & 3) * 2;
        atomicAdd(&ssum[colb], s0[nt][0]);
        atomicAdd(&ssum[colb + 1], s0[nt][1]);
        atomicAdd(&ssum2[colb], s2r[nt][0]);
        atomicAdd(&ssum2[colb + 1], s2r[nt][1]);
    }
    __syncthreads();
    if (tid < 128) {
        atomicAdd(&g_sum[tid], ssum[tid]);
        atomicAdd(&g_sum2[tid], ssum2[tid]);
    }
}

__global__ void k_bn(float* __restrict__ out, const float* __restrict__ gamma,
                     const float* __restrict__ beta, int n) {
    int i = blockIdx.x * blockDim.x + threadIdx.x;
    if (i >= n * 32) return;
    int ob = (i & 31) * 4;
    float inv_n = 1.f / (float)n;
    float4 y = reinterpret_cast<float4*>(out)[i];
    float m0 = g_sum[ob + 0] * inv_n, m1 = g_sum[ob + 1] * inv_n;
    float m2 = g_sum[ob + 2] * inv_n, m3 = g_sum[ob + 3] * inv_n;
    float v0 = g_sum2[ob + 0] * inv_n - m0 * m0;
    float v1 = g_sum2[ob + 1] * inv_n - m1 * m1;
    float v2 = g_sum2[ob + 2] * inv_n - m2 * m2;
    float v3 = g_sum2[ob + 3] * inv_n - m3 * m3;
    y.x = (y.x - m0) * rsqrtf(v0 + BN_EPS) * gamma[ob + 0] + beta[ob + 0];
    y.y = (y.y - m1) * rsqrtf(v1 + BN_EPS) * gamma[ob + 1] + beta[ob + 1];
    y.z = (y.z - m2) * rsqrtf(v2 + BN_EPS) * gamma[ob + 2] + beta[ob + 2];
    y.w = (y.w - m3) * rsqrtf(v3 + BN_EPS) * gamma[ob + 3] + beta[ob + 3];
    reinterpret_cast<float4*>(out)[i] = y;
}

// ---------------- launch ----------------
extern "C" void kernel_launch(void* const* d_in, const int* in_sizes, int n_in,
                              void* d_out, int out_size) {
    const float* feature = (const float*)d_in[0];
    const float* coords  = (const float*)d_in[1];
    const int*   src     = (const int*)d_in[2];
    const int*   dst     = (const int*)d_in[3];
    const int*   order   = (const int*)d_in[4];
    const float* linear  = (const float*)d_in[5];
    const float* attW    = (const float*)d_in[6];
    const float* mlp_w   = (const float*)d_in[7];
    const float* mlp_b   = (const float*)d_in[8];
    const float* bn_gamma = (const float*)d_in[9];
    const float* bn_beta  = (const float*)d_in[10];
    float* out = (float*)d_out;

    int n = in_sizes[0] / F;
    int e = in_sizes[2];

    k_proj<<<(n * 32 + 255) / 256, 256>>>(feature, coords, attW, n);

    int smemp = (128 * 129 + 16 * F) * (int)sizeof(float);
    cudaFuncSetAttribute(k_prep, cudaFuncAttributeMaxDynamicSharedMemorySize, smemp);
    k_prep<<<384 / 16, 128, smemp>>>(linear, mlp_w);

    k_count<<<(e + 255) / 256, 256>>>(dst, e);
    k_scan<<<1, SCAN_B>>>(n, e);
    k_edge<<<(e + 255) / 256, 256>>>(src, dst, order, e);
    k_agg<<<(n * 32 + 255) / 256, 256>>>(n);

    k_out_t<<<(n + 127) / 128, 256>>>(mlp_b, out, n);
    k_bn<<<(n * 32 + 255) / 256, 256>>>(out, bn_gamma, bn_beta, n);
}

// round 16
// speedup vs baseline: 1.1502x; 1.1502x over previous
#include <cuda_runtime.h>
#include <cuda_bf16.h>
#include <cuda_fp16.h>
#include <math.h>

#define NN 50000
#define EE 800000
#define F 128
#define BN_EPS 1e-5f
#define SCAN_B 1024
#define NBLK ((NN + SCAN_B - 1) / SCAN_B)

// ---------------- scratch (16B-aligned where vector-accessed) ----------------
__device__ __align__(16) unsigned g_feath[NN * 64];   // feature as half2 [n][64]
__device__ __align__(16) unsigned g_aggh[NN * 192];   // agg features half2 [n][192]
__device__ __align__(16) unsigned g_Mt[128 * 192];    // M^T half2: [o][k/2]
__device__ __align__(16) float4 g_cp[NN * 2];         // {cx,cy,cz,p0},{p1,p2,-,-}
__device__ float g_sum[F];
__device__ float g_sum2[F];
__device__ float g_den[NN];
__device__ int   g_cnt[NN];
__device__ int   g_bsum[NBLK];
__device__ int   g_off[NN + 1];
__device__ int   g_cur[NN];
__device__ __align__(16) long long g_pack[EE];        // {w (hi), src*4+order (lo)} CSR

__device__ __forceinline__ unsigned h2u(float a, float b) {
    __half2 h = __floats2half2_rn(a, b);
    return *reinterpret_cast<unsigned*>(&h);
}

// ---------------- kernels ----------------
// per-node: proj = attW^T f; pack coords+proj; convert feature to half; zero cnt/den
__global__ void k_proj(const float* __restrict__ feat,
                       const float* __restrict__ coords,
                       const float* __restrict__ attW, int n) {
    int w = (blockIdx.x * blockDim.x + threadIdx.x) >> 5;
    int lane = threadIdx.x & 31;
    if (w >= n) return;
    float4 f = reinterpret_cast<const float4*>(feat + (size_t)w * F)[lane];
    reinterpret_cast<uint2*>(g_feath)[w * 32 + lane] =
        make_uint2(h2u(f.x, f.y), h2u(f.z, f.w));
    const float4* aw = reinterpret_cast<const float4*>(attW);
    float4 w0 = aw[lane], w1 = aw[32 + lane], w2 = aw[64 + lane];
    float a0 = f.x * w0.x + f.y * w0.y + f.z * w0.z + f.w * w0.w;
    float a1 = f.x * w1.x + f.y * w1.y + f.z * w1.z + f.w * w1.w;
    float a2 = f.x * w2.x + f.y * w2.y + f.z * w2.z + f.w * w2.w;
#pragma unroll
    for (int off = 16; off; off >>= 1) {
        a0 += __shfl_down_sync(0xffffffffu, a0, off);
        a1 += __shfl_down_sync(0xffffffffu, a1, off);
        a2 += __shfl_down_sync(0xffffffffu, a2, off);
    }
    if (lane == 0) {
        float cx = coords[w * 3 + 0], cy = coords[w * 3 + 1], cz = coords[w * 3 + 2];
        g_cp[w * 2 + 0] = make_float4(cx, cy, cz, a0);
        g_cp[w * 2 + 1] = make_float4(a1, a2, 0.f, 0.f);
        g_cnt[w] = 0;
        g_den[w] = 0.f;
    }
}

// count pass: histogram of dst
__global__ void k_count(const int* __restrict__ dst, int e) {
    int i = blockIdx.x * blockDim.x + threadIdx.x;
    if (i < e) atomicAdd(&g_cnt[dst[i]], 1);
}

// exclusive block scan via warp shuffles (parallel, 49 blocks)
__global__ void k_scan_block(int n) {
    __shared__ int swarp[32];
    int g = blockIdx.x * SCAN_B + threadIdx.x;
    int lane = threadIdx.x & 31;
    int wid = threadIdx.x >> 5;
    int v = (g < n) ? g_cnt[g] : 0;
    int x = v;
#pragma unroll
    for (int off = 1; off < 32; off <<= 1) {
        int t = __shfl_up_sync(0xffffffffu, x, off);
        if (lane >= off) x += t;
    }
    if (lane == 31) swarp[wid] = x;
    __syncthreads();
    if (wid == 0) {
        int y = swarp[lane];
#pragma unroll
        for (int off = 1; off < 32; off <<= 1) {
            int t = __shfl_up_sync(0xffffffffu, y, off);
            if (lane >= off) y += t;
        }
        swarp[lane] = y;
    }
    __syncthreads();
    int prefix = (wid > 0) ? swarp[wid - 1] : 0;
    int incl = x + prefix;
    if (g < n) g_off[g] = incl - v;
    if (threadIdx.x == SCAN_B - 1) g_bsum[blockIdx.x] = incl;
}
__global__ void k_scan_add(int n, int e) {
    __shared__ int sboff;
    if (threadIdx.x == 0) {
        int acc = 0;
        for (int i = 0; i < (int)blockIdx.x; i++) acc += g_bsum[i];
        sboff = acc;
    }
    __syncthreads();
    int g = blockIdx.x * SCAN_B + threadIdx.x;
    if (g < n) {
        int o = g_off[g] + sboff;
        g_off[g] = o;
        g_cur[g] = o;
    }
    if (g == 0) g_off[n] = e;
}

// edge pass: att/exp/w; den += ex (no-return REDG); CSR scatter of {w,id}
__global__ void k_edge(const int* __restrict__ src, const int* __restrict__ dst,
                       const int* __restrict__ order, int e) {
    int i = blockIdx.x * blockDim.x + threadIdx.x;
    if (i >= e) return;
    int s = src[i], d = dst[i];
    float4 cs0 = g_cp[s * 2 + 0];
    float4 cs1 = g_cp[s * 2 + 1];
    float4 cd0 = g_cp[d * 2 + 0];
    float dx = cs0.x - cd0.x, dy = cs0.y - cd0.y, dz = cs0.z - cd0.z;
    float a = dx * cs0.w + dy * cs1.x + dz * cs1.y;
    float inv = 1.f / (dx * dx + dy * dy + dz * dz + 1.f);
    float ex = __expf(a);
    float w = ex * inv;
    atomicAdd(&g_den[d], ex);
    int pos = atomicAdd(&g_cur[d], 1);
    g_pack[pos] = ((long long)__float_as_int(w) << 32) | (unsigned int)(s * 4 + order[i]);
}

// aggregation: warp per dst; smem-staged records; fp16 feature gathers;
// den read once; no atomics.
__global__ void k_agg(int n) {
    __shared__ long long srec[8][33];
    int wwid = threadIdx.x >> 5;
    int node = (blockIdx.x * blockDim.x + threadIdx.x) >> 5;
    int lane = threadIdx.x & 31;
    if (node >= n) return;
    int beg = g_off[node], end = g_off[node + 1];
    float den = g_den[node];
    float invden = 1.f / (den > 0.f ? den : 1.f);
    float4 a0 = make_float4(0.f, 0.f, 0.f, 0.f);
    float4 a1 = a0, a2 = a0;
    const uint2* f2 = reinterpret_cast<const uint2*>(g_feath);
    for (int base = beg; base < end; base += 32) {
        int idx = base + lane;
        if (idx < end) srec[wwid][lane] = g_pack[idx];
        __syncwarp();
        int cnt = min(32, end - base);
#pragma unroll 4
        for (int j = 0; j < cnt; j++) {
            long long p = srec[wwid][j];
            int id = (int)(unsigned int)p;
            int s = id >> 2, k = id & 3;
            float w = __int_as_float((int)(p >> 32));
            uint2 hv = f2[(size_t)s * 32 + lane];
            __half2 h0 = *reinterpret_cast<__half2*>(&hv.x);
            __half2 h1 = *reinterpret_cast<__half2*>(&hv.y);
            float2 v01 = __half22float2(h0);
            float2 v23 = __half22float2(h1);
            if (k == 0) {
                a0.x += w * v01.x; a0.y += w * v01.y; a0.z += w * v23.x; a0.w += w * v23.y;
            } else if (k == 1) {
                a1.x += w * v01.x; a1.y += w * v01.y; a1.z += w * v23.x; a1.w += w * v23.y;
            } else {
                a2.x += w * v01.x; a2.y += w * v01.y; a2.z += w * v23.x; a2.w += w * v23.y;
            }
        }
        __syncwarp();
    }
    uint2* gp = reinterpret_cast<uint2*>(g_aggh);
    gp[node * 96 +  0 + lane] = make_uint2(h2u(a0.x * invden, a0.y * invden),
                                           h2u(a0.z * invden, a0.w * invden));
    gp[node * 96 + 32 + lane] = make_uint2(h2u(a1.x * invden, a1.y * invden),
                                           h2u(a1.z * invden, a1.w * invden));
    gp[node * 96 + 64 + lane] = make_uint2(h2u(a2.x * invden, a2.y * invden),
                                           h2u(a2.z * invden, a2.w * invden));
}

// fold: M[r][o] = sum_j linear[r][j]*mlp_w[o][j]; store half TRANSPOSED [o][k/2]
__global__ void k_prep(const float* __restrict__ lin, const float* __restrict__ W) {
    extern __shared__ float smem[];
    float* swT = smem;              // [128][129]
    float* sL = smem + 128 * 129;   // [16][128]
    int t = threadIdx.x;
    int r0 = blockIdx.x * 16;
    if (blockIdx.x == 0) { g_sum[t] = 0.f; g_sum2[t] = 0.f; }
#pragma unroll 4
    for (int j = 0; j < F; j++)
        swT[t * 129 + j] = W[j * F + t];
    for (int idx = t; idx < 16 * F; idx += F)
        sL[idx] = lin[(size_t)r0 * F + idx];
    __syncthreads();
    float acc[16];
#pragma unroll
    for (int r = 0; r < 16; r++) acc[r] = 0.f;
#pragma unroll 4
    for (int j = 0; j < F; j++) {
        float wv = swT[j * 129 + t];
#pragma unroll
        for (int r = 0; r < 16; r++) acc[r] += sL[r * F + j] * wv;
    }
#pragma unroll
    for (int j = 0; j < 8; j++)
        g_Mt[t * 192 + r0 / 2 + j] = h2u(acc[2 * j], acc[2 * j + 1]);
}

// fused output GEMM (fp16 tensor cores m16n8k16, fp32 accum)
__global__ void __launch_bounds__(256, 2)
k_out_t(const float* __restrict__ mlp_b, float* __restrict__ out, int n) {
    __shared__ unsigned As2[128 * 20];
    __shared__ unsigned Bs2[128 * 20];
    __shared__ float ssum[128], ssum2[128];
    int tid = threadIdx.x;
    int lane = tid & 31;
    int wid = tid >> 5;
    int wm = wid >> 1;
    int wn = wid & 1;
    int row0 = blockIdx.x * 128;

    if (tid < 128) { ssum[tid] = 0.f; ssum2[tid] = 0.f; }

    float c[2][8][4];
#pragma unroll
    for (int i = 0; i < 2; i++)
#pragma unroll
        for (int j = 0; j < 8; j++)
#pragma unroll
            for (int q = 0; q < 4; q++) c[i][j][q] = 0.f;

    int arow[2], aq[2];
#pragma unroll
    for (int i = 0; i < 2; i++) {
        int lidx = i * 256 + tid;
        arow[i] = lidx >> 2;
        aq[i] = (lidx & 3) * 4;
    }

    uint4 pa[2], pb[2];
#pragma unroll
    for (int i = 0; i < 2; i++) {
        pa[i] = make_uint4(0, 0, 0, 0);
        if (row0 + arow[i] < n)
            pa[i] = *reinterpret_cast<const uint4*>(g_aggh + (size_t)(row0 + arow[i]) * 192 + aq[i]);
        pb[i] = *reinterpret_cast<const uint4*>(g_Mt + (size_t)arow[i] * 192 + aq[i]);
    }

    for (int k0 = 0; k0 < 384; k0 += 32) {
        __syncthreads();
#pragma unroll
        for (int i = 0; i < 2; i++) {
            unsigned* ap = &As2[arow[i] * 20 + aq[i]];
            ap[0] = pa[i].x; ap[1] = pa[i].y; ap[2] = pa[i].z; ap[3] = pa[i].w;
            unsigned* bp = &Bs2[arow[i] * 20 + aq[i]];
            bp[0] = pb[i].x; bp[1] = pb[i].y; bp[2] = pb[i].z; bp[3] = pb[i].w;
        }
        __syncthreads();

        int kn = k0 + 32;
        if (kn < 384) {
            int kb = kn >> 1;
#pragma unroll
            for (int i = 0; i < 2; i++) {
                pa[i] = make_uint4(0, 0, 0, 0);
                if (row0 + arow[i] < n)
                    pa[i] = *reinterpret_cast<const uint4*>(g_aggh + (size_t)(row0 + arow[i]) * 192 + kb + aq[i]);
                pb[i] = *reinterpret_cast<const uint4*>(g_Mt + (size_t)arow[i] * 192 + kb + aq[i]);
            }
        }

#pragma unroll
        for (int kofs = 0; kofs < 16; kofs += 8) {
            unsigned a[2][4];
#pragma unroll
            for (int mt = 0; mt < 2; mt++) {
                int r = wm * 32 + mt * 16 + (lane >> 2);
                int kp = kofs + (lane & 3);
                a[mt][0] = As2[r * 20 + kp];
                a[mt][1] = As2[(r + 8) * 20 + kp];
                a[mt][2] = As2[r * 20 + kp + 4];
                a[mt][3] = As2[(r + 8) * 20 + kp + 4];
            }
#pragma unroll
            for (int nt = 0; nt < 8; nt++) {
                int col = wn * 64 + nt * 8 + (lane >> 2);
                int kp = kofs + (lane & 3);
                unsigned b0 = Bs2[col * 20 + kp];
                unsigned b1 = Bs2[col * 20 + kp + 4];
#pragma unroll
                for (int mt = 0; mt < 2; mt++) {
                    asm volatile(
                        "mma.sync.aligned.m16n8k16.row.col.f32.f16.f16.f32 "
                        "{%0,%1,%2,%3}, {%4,%5,%6,%7}, {%8,%9}, {%0,%1,%2,%3};"
                        : "+f"(c[mt][nt][0]), "+f"(c[mt][nt][1]),
                          "+f"(c[mt][nt][2]), "+f"(c[mt][nt][3])
                        : "r"(a[mt][0]), "r"(a[mt][1]), "r"(a[mt][2]), "r"(a[mt][3]),
                          "r"(b0), "r"(b1));
                }
            }
        }
    }
    __syncthreads();

    float s0[8][2], s2r[8][2];
#pragma unroll
    for (int nt = 0; nt < 8; nt++) {
        s0[nt][0] = 0.f; s0[nt][1] = 0.f;
        s2r[nt][0] = 0.f; s2r[nt][1] = 0.f;
    }
#pragma unroll
    for (int nt = 0; nt < 8; nt++) {
        int colb = wn * 64 + nt * 8 + (lane & 3) * 2;
        float b0 = mlp_b[colb], b1 = mlp_b[colb + 1];
#pragma unroll
        for (int mt = 0; mt < 2; mt++) {
            int rowa = row0 + wm * 32 + mt * 16 + (lane >> 2);
#pragma unroll
            for (int h = 0; h < 2; h++) {
                int row = rowa + h * 8;
                if (row >= n) continue;
                float y0 = c[mt][nt][h * 2 + 0] + b0;
                float y1 = c[mt][nt][h * 2 + 1] + b1;
                y0 = y0 > 0.f ? y0 : 0.f;
                y1 = y1 > 0.f ? y1 : 0.f;
                out[(size_t)row * F + colb] = y0;
                out[(size_t)row * F + colb + 1] = y1;
                s0[nt][0] += y0; s0[nt][1] += y1;
                s2r[nt][0] += y0 * y0; s2r[nt][1] += y1 * y1;
            }
        }
    }
#pragma unroll
    for (int nt = 0; nt < 8; nt++) {
        int colb = wn * 64 + nt * 8 + (lane & 3) * 2;
        atomicAdd(&ssum[colb], s0[nt][0]);
        atomicAdd(&ssum[colb + 1], s0[nt][1]);
        atomicAdd(&ssum2[colb], s2r[nt][0]);
        atomicAdd(&ssum2[colb + 1], s2r[nt][1]);
    }
    __syncthreads();
    if (tid < 128) {
        atomicAdd(&g_sum[tid], ssum[tid]);
        atomicAdd(&g_sum2[tid], ssum2[tid]);
    }
}

__global__ void k_bn(float* __restrict__ out, const float* __restrict__ gamma,
                     const float* __restrict__ beta, int n) {
    int i = blockIdx.x * blockDim.x + threadIdx.x;
    if (i >= n * 32) return;
    int ob = (i & 31) * 4;
    float inv_n = 1.f / (float)n;
    float4 y = reinterpret_cast<float4*>(out)[i];
    float m0 = g_sum[ob + 0] * inv_n, m1 = g_sum[ob + 1] * inv_n;
    float m2 = g_sum[ob + 2] * inv_n, m3 = g_sum[ob + 3] * inv_n;
    float v0 = g_sum2[ob + 0] * inv_n - m0 * m0;
    float v1 = g_sum2[ob + 1] * inv_n - m1 * m1;
    float v2 = g_sum2[ob + 2] * inv_n - m2 * m2;
    float v3 = g_sum2[ob + 3] * inv_n - m3 * m3;
    y.x = (y.x - m0) * rsqrtf(v0 + BN_EPS) * gamma[ob + 0] + beta[ob + 0];
    y.y = (y.y - m1) * rsqrtf(v1 + BN_EPS) * gamma[ob + 1] + beta[ob + 1];
    y.z = (y.z - m2) * rsqrtf(v2 + BN_EPS) * gamma[ob + 2] + beta[ob + 2];
    y.w = (y.w - m3) * rsqrtf(v3 + BN_EPS) * gamma[ob + 3] + beta[ob + 3];
    reinterpret_cast<float4*>(out)[i] = y;
}

// ---------------- launch ----------------
extern "C" void kernel_launch(void* const* d_in, const int* in_sizes, int n_in,
                              void* d_out, int out_size) {
    const float* feature = (const float*)d_in[0];
    const float* coords  = (const float*)d_in[1];
    const int*   src     = (const int*)d_in[2];
    const int*   dst     = (const int*)d_in[3];
    const int*   order   = (const int*)d_in[4];
    const float* linear  = (const float*)d_in[5];
    const float* attW    = (const float*)d_in[6];
    const float* mlp_w   = (const float*)d_in[7];
    const float* mlp_b   = (const float*)d_in[8];
    const float* bn_gamma = (const float*)d_in[9];
    const float* bn_beta  = (const float*)d_in[10];
    float* out = (float*)d_out;

    int n = in_sizes[0] / F;
    int e = in_sizes[2];
    int nb = (n + SCAN_B - 1) / SCAN_B;

    k_proj<<<(n * 32 + 255) / 256, 256>>>(feature, coords, attW, n);

    int smemp = (128 * 129 + 16 * F) * (int)sizeof(float);
    cudaFuncSetAttribute(k_prep, cudaFuncAttributeMaxDynamicSharedMemorySize, smemp);
    k_prep<<<384 / 16, 128, smemp>>>(linear, mlp_w);

    k_count<<<(e + 255) / 256, 256>>>(dst, e);
    k_scan_block<<<nb, SCAN_B>>>(n);
    k_scan_add<<<nb, SCAN_B>>>(n, e);
    k_edge<<<(e + 255) / 256, 256>>>(src, dst, order, e);
    k_agg<<<(n * 32 + 255) / 256, 256>>>(n);

    k_out_t<<<(n + 127) / 128, 256>>>(mlp_b, out, n);
    k_bn<<<(n * 32 + 255) / 256, 256>>>(out, bn_gamma, bn_beta, n);
}